// round 10
// baseline (speedup 1.0000x reference)
#include <cuda_runtime.h>
#include <cuda_bf16.h>
#include <cstdint>
#include <cstddef>
#include <mma.h>

using namespace nvcuda;

#define B_    8192
#define NNEG  8192
#define D_    1024

#define BM 128
#define BN 256
#define BK 128                  // s8 elems per K-chunk (=128 bytes/row)
#define LDK 144                 // smem row stride in bytes (9*16 -> conflict-free)
#define NIT    (D_ / BK)        // 8
#define NTILES (NNEG / BN)      // 32

#define A_STAGE_B (BM * LDK)                // 18432 B
#define B_STAGE_B (BN * LDK)                // 36864 B
#define STAGE_B   (A_STAGE_B + B_STAGE_B)   // 55296 B
#define PIPE_BYTES (2 * STAGE_B)            // 110592
#define EPI_LD 260
#define CS_OFF  (BM * EPI_LD * 4)           // 133120
#define EPI_BYTES (CS_OFF + BN * 4)         // +1KB col scales
#define SMEM_BYTES (EPI_BYTES > PIPE_BYTES ? EPI_BYTES : PIPE_BYTES)

__device__ __align__(16) int8_t g_Qs8[(size_t)B_ * D_];   // 8 MB quantized Q
__device__ __align__(16) int8_t g_Ns8[(size_t)NNEG * D_]; // 8 MB quantized N
__device__ float g_Qsc[B_];     // per-row dequant scale (vmax/127)
__device__ float g_Nsc[NNEG];
__device__ float g_pos[B_];
__device__ float g_part[(size_t)B_ * NTILES];
__device__ float g_row[B_];

__constant__ float c_invT = 1.0f / 0.92f;

// ---------------------------------------------------------------------------
// Kernel 1: per-row ||q||,||p||,q.p -> pos_sim; quantize normalized Q to s8
// grid = B_, block = 256
// ---------------------------------------------------------------------------
__global__ void k_norm_qp(const float* __restrict__ q, const float* __restrict__ p) {
    int b = blockIdx.x, t = threadIdx.x;
    float4 a = reinterpret_cast<const float4*>(q + (size_t)b * D_)[t];
    float4 c = reinterpret_cast<const float4*>(p + (size_t)b * D_)[t];

    float qq = a.x*a.x + a.y*a.y + a.z*a.z + a.w*a.w;
    float pp = c.x*c.x + c.y*c.y + c.z*c.z + c.w*c.w;
    float qp = a.x*c.x + a.y*c.y + a.z*c.z + a.w*c.w;
    #pragma unroll
    for (int o = 16; o > 0; o >>= 1) {
        qq += __shfl_xor_sync(0xffffffffu, qq, o);
        pp += __shfl_xor_sync(0xffffffffu, pp, o);
        qp += __shfl_xor_sync(0xffffffffu, qp, o);
    }
    __shared__ float sq[8], sp[8], sc[8];
    __shared__ float s_inv, s_qs;
    int w = t >> 5, l = t & 31;
    if (l == 0) { sq[w] = qq; sp[w] = pp; sc[w] = qp; }
    __syncthreads();
    if (t == 0) {
        float QQ = 0.f, PP = 0.f, QP = 0.f;
        #pragma unroll
        for (int i = 0; i < 8; i++) { QQ += sq[i]; PP += sp[i]; QP += sc[i]; }
        float qn = sqrtf(QQ), pn = sqrtf(PP);
        g_pos[b] = QP / fmaxf(qn * pn, 1e-6f);
        s_inv = (qn > 0.f) ? (1.0f / qn) : 0.f;
    }
    __syncthreads();
    float inv = s_inv;
    float nx = a.x * inv, ny = a.y * inv, nz = a.z * inv, nw = a.w * inv;

    // row max of |normalized|
    float m = fmaxf(fmaxf(fabsf(nx), fabsf(ny)), fmaxf(fabsf(nz), fabsf(nw)));
    #pragma unroll
    for (int o = 16; o > 0; o >>= 1) m = fmaxf(m, __shfl_xor_sync(0xffffffffu, m, o));
    if (l == 0) sq[w] = m;
    __syncthreads();
    if (t == 0) {
        float vmax = 0.f;
        #pragma unroll
        for (int i = 0; i < 8; i++) vmax = fmaxf(vmax, sq[i]);
        g_Qsc[b] = vmax * (1.0f / 127.0f);
        s_qs = (vmax > 0.f) ? (127.0f / vmax) : 0.f;
    }
    __syncthreads();
    float qs = s_qs;
    char4 pk;
    pk.x = (char)__float2int_rn(nx * qs);
    pk.y = (char)__float2int_rn(ny * qs);
    pk.z = (char)__float2int_rn(nz * qs);
    pk.w = (char)__float2int_rn(nw * qs);
    reinterpret_cast<char4*>(g_Qs8)[(size_t)b * 256 + t] = pk;
}

// ---------------------------------------------------------------------------
// Kernel 2: per-row ||n|| -> quantized s8 N + scale
// ---------------------------------------------------------------------------
__global__ void k_norm_n(const float* __restrict__ n) {
    int b = blockIdx.x, t = threadIdx.x;
    float4 a = reinterpret_cast<const float4*>(n + (size_t)b * D_)[t];
    float nn = a.x*a.x + a.y*a.y + a.z*a.z + a.w*a.w;
    #pragma unroll
    for (int o = 16; o > 0; o >>= 1) nn += __shfl_xor_sync(0xffffffffu, nn, o);
    __shared__ float sn[8];
    __shared__ float s_inv, s_qs;
    int w = t >> 5, l = t & 31;
    if (l == 0) sn[w] = nn;
    __syncthreads();
    if (t == 0) {
        float NN = 0.f;
        #pragma unroll
        for (int i = 0; i < 8; i++) NN += sn[i];
        float qn = sqrtf(NN);
        s_inv = (qn > 0.f) ? (1.0f / qn) : 0.f;
    }
    __syncthreads();
    float inv = s_inv;
    float nx = a.x * inv, ny = a.y * inv, nz = a.z * inv, nw = a.w * inv;

    float m = fmaxf(fmaxf(fabsf(nx), fabsf(ny)), fmaxf(fabsf(nz), fabsf(nw)));
    #pragma unroll
    for (int o = 16; o > 0; o >>= 1) m = fmaxf(m, __shfl_xor_sync(0xffffffffu, m, o));
    if (l == 0) sn[w] = m;
    __syncthreads();
    if (t == 0) {
        float vmax = 0.f;
        #pragma unroll
        for (int i = 0; i < 8; i++) vmax = fmaxf(vmax, sn[i]);
        g_Nsc[b] = vmax * (1.0f / 127.0f);
        s_qs = (vmax > 0.f) ? (127.0f / vmax) : 0.f;
    }
    __syncthreads();
    float qs = s_qs;
    char4 pk;
    pk.x = (char)__float2int_rn(nx * qs);
    pk.y = (char)__float2int_rn(ny * qs);
    pk.z = (char)__float2int_rn(nz * qs);
    pk.w = (char)__float2int_rn(nw * qs);
    reinterpret_cast<char4*>(g_Ns8)[(size_t)b * 256 + t] = pk;
}

// ---------------------------------------------------------------------------
// poly exp on [-1.09, 1.09] (deg-9 Taylor, FMA pipe only)
// ---------------------------------------------------------------------------
__device__ __forceinline__ float poly_exp(float x) {
    float e = 2.7557319e-6f;
    e = fmaf(e, x, 2.4801587e-5f);
    e = fmaf(e, x, 1.9841270e-4f);
    e = fmaf(e, x, 1.3888889e-3f);
    e = fmaf(e, x, 8.3333333e-3f);
    e = fmaf(e, x, 4.1666668e-2f);
    e = fmaf(e, x, 1.6666667e-1f);
    e = fmaf(e, x, 0.5f);
    e = fmaf(e, x, 1.0f);
    e = fmaf(e, x, 1.0f);
    return e;
}

__device__ __forceinline__ void cpa16(uint32_t dst_smem, const void* src) {
    asm volatile("cp.async.cg.shared.global [%0], [%1], 16;" :: "r"(dst_smem), "l"(src));
}
__device__ __forceinline__ void cp_commit() { asm volatile("cp.async.commit_group;"); }

// ---------------------------------------------------------------------------
// Kernel 3: s8 IMMA GEMM, 128x256 block tile, 32x64 warp tile, BK=128,
// double-buffered cp.async, fused dequant + poly-exp + row partials.
// grid = (NNEG/256, B_/128), block = 512 (16 warps as 4x4)
// ---------------------------------------------------------------------------
__global__ __launch_bounds__(512, 1) void k_gemm() {
    extern __shared__ __align__(16) char smem_raw[];
    int8_t* Sb = reinterpret_cast<int8_t*>(smem_raw);
    int*    Cb = reinterpret_cast<int*>(smem_raw);
    float*  csm = reinterpret_cast<float*>(smem_raw + CS_OFF);
    const uint32_t sbase = (uint32_t)__cvta_generic_to_shared(smem_raw);

    const int t = threadIdx.x;
    const int warp = t >> 5;
    const int wm = warp >> 2;     // 0..3 : 32-row strip
    const int wn = warp & 3;      // 0..3 : 64-col strip
    const int bx = blockIdx.x, by = blockIdx.y;

    const int8_t* Aptr = g_Qs8 + (size_t)by * BM * D_;
    const int8_t* Bptr = g_Ns8 + (size_t)bx * BN * D_;

    // loader: A = 1024 16B chunks (2/thread), B = 2048 chunks (4/thread)
    auto load_stage = [&](int s, int k0) {
        uint32_t Abase = sbase + (uint32_t)s * STAGE_B;
        uint32_t Bbase = Abase + A_STAGE_B;
        #pragma unroll
        for (int i = 0; i < 2; i++) {
            int c = t + 512 * i;
            int r = c >> 3, c16 = c & 7;
            cpa16(Abase + (uint32_t)(r * LDK + c16 * 16),
                  Aptr + (size_t)r * D_ + k0 + c16 * 16);
        }
        #pragma unroll
        for (int i = 0; i < 4; i++) {
            int c = t + 512 * i;
            int r = c >> 3, c16 = c & 7;
            cpa16(Bbase + (uint32_t)(r * LDK + c16 * 16),
                  Bptr + (size_t)r * D_ + k0 + c16 * 16);
        }
    };

    wmma::fragment<wmma::accumulator, 16, 16, 16, int> acc[2][4];
    #pragma unroll
    for (int i = 0; i < 2; i++)
        #pragma unroll
        for (int j = 0; j < 4; j++)
            wmma::fill_fragment(acc[i][j], 0);

    load_stage(0, 0);
    cp_commit();

    for (int it = 0; it < NIT; it++) {
        const int cur = it & 1;
        if (it + 1 < NIT) load_stage(cur ^ 1, (it + 1) * BK);
        cp_commit();
        if (it + 1 < NIT) asm volatile("cp.async.wait_group 1;");
        else              asm volatile("cp.async.wait_group 0;");
        __syncthreads();

        const int8_t* Ab = Sb + (size_t)cur * STAGE_B;
        const int8_t* Bb = Ab + A_STAGE_B;
        #pragma unroll
        for (int kk = 0; kk < BK; kk += 16) {
            wmma::fragment<wmma::matrix_a, 16, 16, 16, signed char, wmma::row_major> af[2];
            wmma::fragment<wmma::matrix_b, 16, 16, 16, signed char, wmma::col_major> bfg[4];
            #pragma unroll
            for (int i = 0; i < 2; i++)
                wmma::load_matrix_sync(af[i],
                    reinterpret_cast<const signed char*>(Ab + (size_t)(wm * 32 + 16 * i) * LDK + kk), LDK);
            #pragma unroll
            for (int j = 0; j < 4; j++)
                wmma::load_matrix_sync(bfg[j],
                    reinterpret_cast<const signed char*>(Bb + (size_t)(wn * 64 + 16 * j) * LDK + kk), LDK);
            #pragma unroll
            for (int i = 0; i < 2; i++)
                #pragma unroll
                for (int j = 0; j < 4; j++)
                    wmma::mma_sync(acc[i][j], af[i], bfg[j], acc[i][j]);
        }
        __syncthreads();
    }

    // Epilogue: dump int accumulators to smem (pipeline buffers dead)
    #pragma unroll
    for (int i = 0; i < 2; i++)
        #pragma unroll
        for (int j = 0; j < 4; j++)
            wmma::store_matrix_sync(&Cb[(size_t)(wm * 32 + 16 * i) * EPI_LD + wn * 64 + 16 * j],
                                    acc[i][j], EPI_LD, wmma::mem_row_major);
    if (t < BN) csm[t] = g_Nsc[(size_t)bx * BN + t];
    __syncthreads();

    // dequant + exp + row partial sums: 4 threads per row, 64 cols each
    const int row = t >> 2, seg = t & 3;
    const float rsT = g_Qsc[(size_t)by * BM + row] * c_invT;
    const int* cr = &Cb[(size_t)row * EPI_LD + seg * 64];
    const float* cs = &csm[seg * 64];
    float s = 0.f;
    #pragma unroll
    for (int j = 0; j < 64; j++)
        s += poly_exp((float)cr[j] * rsT * cs[j]);
    s += __shfl_xor_sync(0xffffffffu, s, 1);
    s += __shfl_xor_sync(0xffffffffu, s, 2);
    if (seg == 0)
        g_part[(size_t)(by * BM + row) * NTILES + bx] = s;  // deterministic
}

// ---------------------------------------------------------------------------
// Kernel 4a: per-row loss term (8192 threads)
// ---------------------------------------------------------------------------
__global__ void k_rowloss() {
    int b = blockIdx.x * 256 + threadIdx.x;
    const float4* pr = reinterpret_cast<const float4*>(&g_part[(size_t)b * NTILES]);
    float s2s = 0.f;
    #pragma unroll
    for (int j = 0; j < NTILES / 4; j++) {
        float4 v = pr[j];
        s2s += v.x + v.y + v.z + v.w;
    }
    float s2 = s2s * (1.0f / (float)NNEG);
    float s1 = expf(g_pos[b] * c_invT);
    g_row[b] = log1pf(s2 / s1);
}

// ---------------------------------------------------------------------------
// Kernel 4b: final scalar reduce
// ---------------------------------------------------------------------------
__global__ void k_reduce(float* __restrict__ out) {
    int t = threadIdx.x;
    double acc = 0.0;
    #pragma unroll
    for (int j = 0; j < 32; j++)
        acc += (double)g_row[t + j * 256];
    #pragma unroll
    for (int o = 16; o > 0; o >>= 1) acc += __shfl_xor_sync(0xffffffffu, acc, o);
    __shared__ double sd[8];
    if ((t & 31) == 0) sd[t >> 5] = acc;
    __syncthreads();
    if (t == 0) {
        double tot = 0.0;
        #pragma unroll
        for (int i = 0; i < 8; i++) tot += sd[i];
        out[0] = (float)(tot / (double)B_);
    }
}

// ---------------------------------------------------------------------------
extern "C" void kernel_launch(void* const* d_in, const int* in_sizes, int n_in,
                              void* d_out, int out_size) {
    const float* q = (const float*)d_in[0];
    const float* p = (const float*)d_in[1];
    const float* n = (const float*)d_in[2];
    float* out = (float*)d_out;

    cudaFuncSetAttribute(k_gemm, cudaFuncAttributeMaxDynamicSharedMemorySize, SMEM_BYTES);

    k_norm_qp<<<B_, 256>>>(q, p);
    k_norm_n<<<NNEG, 256>>>(n);
    k_gemm<<<dim3(NNEG / BN, B_ / BM), 512, SMEM_BYTES>>>();
    k_rowloss<<<B_ / 256, 256>>>();
    k_reduce<<<1, 256>>>(out);
}

// round 11
// speedup vs baseline: 4.4247x; 4.4247x over previous
#include <cuda_runtime.h>
#include <cuda_bf16.h>
#include <cstdint>
#include <cstddef>

#define B_    8192
#define NNEG  8192
#define D_    1024

#define BM 128
#define BN 128
#define BK 64
#define NIT    (D_ / BK)     // 16
#define NTILES (NNEG / BN)   // 64

#define LDK 144              // smem row stride bytes (conflict-free ldmatrix)
#define STAGE_B (256 * LDK)  // A(128 rows)+B(128 rows) = 36864 B
#define NSTAGE 3
#define SMEM_BYTES (NSTAGE * STAGE_B)   // 110592
#define EPI_LD 132

__device__ __align__(16) __nv_bfloat16 g_Qh[(size_t)B_ * D_];
__device__ __align__(16) __nv_bfloat16 g_Nh[(size_t)NNEG * D_];
__device__ float g_pos[B_];
__device__ float g_part[(size_t)B_ * NTILES];
__device__ float g_row[B_];

__constant__ float c_invT = 1.0f / 0.92f;

// ---------------------------------------------------------------------------
// Kernel 1: per-row ||q||, ||p||, q.p -> pos_sim, normalized bf16 Q
// ---------------------------------------------------------------------------
__global__ void k_norm_qp(const float* __restrict__ q, const float* __restrict__ p) {
    int b = blockIdx.x, t = threadIdx.x;
    float4 a = reinterpret_cast<const float4*>(q + (size_t)b * D_)[t];
    float4 c = reinterpret_cast<const float4*>(p + (size_t)b * D_)[t];

    float qq = a.x*a.x + a.y*a.y + a.z*a.z + a.w*a.w;
    float pp = c.x*c.x + c.y*c.y + c.z*c.z + c.w*c.w;
    float qp = a.x*c.x + a.y*c.y + a.z*c.z + a.w*c.w;
    #pragma unroll
    for (int o = 16; o > 0; o >>= 1) {
        qq += __shfl_xor_sync(0xffffffffu, qq, o);
        pp += __shfl_xor_sync(0xffffffffu, pp, o);
        qp += __shfl_xor_sync(0xffffffffu, qp, o);
    }
    __shared__ float sq[8], sp[8], sc[8];
    __shared__ float s_inv;
    int w = t >> 5, l = t & 31;
    if (l == 0) { sq[w] = qq; sp[w] = pp; sc[w] = qp; }
    __syncthreads();
    if (t == 0) {
        float QQ = 0.f, PP = 0.f, QP = 0.f;
        #pragma unroll
        for (int i = 0; i < 8; i++) { QQ += sq[i]; PP += sp[i]; QP += sc[i]; }
        float qn = sqrtf(QQ), pn = sqrtf(PP);
        g_pos[b] = QP / fmaxf(qn * pn, 1e-6f);
        s_inv = (qn > 0.f) ? (1.0f / qn) : 0.f;
    }
    __syncthreads();
    float inv = s_inv;
    __nv_bfloat162 lo = __floats2bfloat162_rn(a.x * inv, a.y * inv);
    __nv_bfloat162 hi = __floats2bfloat162_rn(a.z * inv, a.w * inv);
    __nv_bfloat162* dst = reinterpret_cast<__nv_bfloat162*>(g_Qh) + (size_t)b * (D_ / 2) + t * 2;
    dst[0] = lo; dst[1] = hi;
}

// ---------------------------------------------------------------------------
// Kernel 2: per-row ||n|| -> normalized bf16 N
// ---------------------------------------------------------------------------
__global__ void k_norm_n(const float* __restrict__ n) {
    int b = blockIdx.x, t = threadIdx.x;
    float4 a = reinterpret_cast<const float4*>(n + (size_t)b * D_)[t];
    float nn = a.x*a.x + a.y*a.y + a.z*a.z + a.w*a.w;
    #pragma unroll
    for (int o = 16; o > 0; o >>= 1) nn += __shfl_xor_sync(0xffffffffu, nn, o);
    __shared__ float sn[8];
    __shared__ float s_inv;
    int w = t >> 5, l = t & 31;
    if (l == 0) sn[w] = nn;
    __syncthreads();
    if (t == 0) {
        float NN = 0.f;
        #pragma unroll
        for (int i = 0; i < 8; i++) NN += sn[i];
        float qn = sqrtf(NN);
        s_inv = (qn > 0.f) ? (1.0f / qn) : 0.f;
    }
    __syncthreads();
    float inv = s_inv;
    __nv_bfloat162 lo = __floats2bfloat162_rn(a.x * inv, a.y * inv);
    __nv_bfloat162 hi = __floats2bfloat162_rn(a.z * inv, a.w * inv);
    __nv_bfloat162* dst = reinterpret_cast<__nv_bfloat162*>(g_Nh) + (size_t)b * (D_ / 2) + t * 2;
    dst[0] = lo; dst[1] = hi;
}

// ---------------------------------------------------------------------------
// poly exp on [-1.2, 1.2] (deg-9 Taylor, FMA pipe only)
// ---------------------------------------------------------------------------
__device__ __forceinline__ float poly_exp(float x) {
    float e = 2.7557319e-6f;
    e = fmaf(e, x, 2.4801587e-5f);
    e = fmaf(e, x, 1.9841270e-4f);
    e = fmaf(e, x, 1.3888889e-3f);
    e = fmaf(e, x, 8.3333333e-3f);
    e = fmaf(e, x, 4.1666668e-2f);
    e = fmaf(e, x, 1.6666667e-1f);
    e = fmaf(e, x, 0.5f);
    e = fmaf(e, x, 1.0f);
    e = fmaf(e, x, 1.0f);
    return e;
}

__device__ __forceinline__ void cpa16(uint32_t dst_smem, const void* src) {
    asm volatile("cp.async.cg.shared.global [%0], [%1], 16;" :: "r"(dst_smem), "l"(src));
}

#define LDSM4(r0, r1, r2, r3, addr) \
    asm volatile("ldmatrix.sync.aligned.m8n8.x4.shared.b16 {%0,%1,%2,%3}, [%4];" \
        : "=r"(r0), "=r"(r1), "=r"(r2), "=r"(r3) : "r"(addr))

#define MMA_BF16(d, av, b0, b1) \
    asm volatile("mma.sync.aligned.m16n8k16.row.col.f32.bf16.bf16.f32 " \
        "{%0,%1,%2,%3}, {%4,%5,%6,%7}, {%8,%9}, {%0,%1,%2,%3};" \
        : "+f"((d)[0]), "+f"((d)[1]), "+f"((d)[2]), "+f"((d)[3]) \
        : "r"((av)[0]), "r"((av)[1]), "r"((av)[2]), "r"((av)[3]), "r"(b0), "r"(b1))

// ---------------------------------------------------------------------------
// Kernel 3: bf16 mma.sync GEMM, 128x128 block tile, 32x32 warp tile, BK=64,
// 3-stage cp.async pipeline, register fragment double-buffering,
// single barrier per K-iteration, fused poly-exp + deterministic partials.
// grid = (NNEG/128, B_/128), block = 512 (16 warps as 4x4)
// ---------------------------------------------------------------------------
__global__ __launch_bounds__(512, 1) void k_gemm() {
    extern __shared__ __align__(16) char smem_raw[];
    float* Cf = reinterpret_cast<float*>(smem_raw);
    const uint32_t sbase = (uint32_t)__cvta_generic_to_shared(smem_raw);

    const int t = threadIdx.x;
    const int warp = t >> 5, lane = t & 31;
    const int wm = warp >> 2;   // 0..3 : 32-row strip
    const int wn = warp & 3;    // 0..3 : 32-col strip
    const int bx = blockIdx.x, by = blockIdx.y;

    const __nv_bfloat16* Aptr = g_Qh + (size_t)by * BM * D_;
    const __nv_bfloat16* Bptr = g_Nh + (size_t)bx * BN * D_;

    // --- stage loader: 2048 16B chunks, 4 per thread (i 0,1 = A; 2,3 = B)
    auto load_stage = [&](int slot, int k0) {
        uint32_t base = sbase + (uint32_t)slot * STAGE_B;
        #pragma unroll
        for (int i = 0; i < 2; i++) {
            int c = t + 512 * i;
            int r = c >> 3, c16 = c & 7;
            cpa16(base + (uint32_t)(r * LDK + c16 * 16),
                  Aptr + (size_t)r * D_ + k0 + c16 * 8);
        }
        #pragma unroll
        for (int i = 2; i < 4; i++) {
            int c = t + 512 * i;
            int r = c >> 3, c16 = c & 7;
            cpa16(base + (uint32_t)(r * LDK + c16 * 16),
                  Bptr + (size_t)(r - 128) * D_ + k0 + c16 * 8);
        }
        asm volatile("cp.async.commit_group;");
    };

    // ldmatrix per-thread address components
    const uint32_t lrow16 = (uint32_t)((lane & 7) | (((lane >> 3) & 1) << 3)); // 0..15
    const uint32_t lbyteA = (uint32_t)((lane >> 4) * 16);                       // A k-half
    const int btile = lane >> 3, bnrow = lane & 7;                              // B tiles

    // A row byte-offset (within stage) for strip s: (wm*32 + s*16 + lrow16)*LDK
    uint32_t aoff[2], boff[2];
    #pragma unroll
    for (int s = 0; s < 2; s++)
        aoff[s] = (uint32_t)((wm * 32 + s * 16 + (int)lrow16) * LDK) + lbyteA;
    #pragma unroll
    for (int p = 0; p < 2; p++) {
        int strip = 2 * p + (btile >> 1);
        boff[p] = (uint32_t)(128 * LDK + (wn * 32 + strip * 8 + bnrow) * LDK
                             + (btile & 1) * 16);
    }

    uint32_t afr[2][2][4];   // [buf][strip][reg]
    uint32_t bfr[2][2][4];   // [buf][pair][reg] : pair p -> strips 2p (r0,r1), 2p+1 (r2,r3)
    float acc[2][4][4] = {}; // [mi][nj][reg]

    auto load_frags = [&](uint32_t base, int kk, int buf) {
        uint32_t ko = (uint32_t)(kk * 32);
        #pragma unroll
        for (int s = 0; s < 2; s++)
            LDSM4(afr[buf][s][0], afr[buf][s][1], afr[buf][s][2], afr[buf][s][3],
                  base + aoff[s] + ko);
        #pragma unroll
        for (int p = 0; p < 2; p++)
            LDSM4(bfr[buf][p][0], bfr[buf][p][1], bfr[buf][p][2], bfr[buf][p][3],
                  base + boff[p] + ko);
    };

    load_stage(0, 0);
    load_stage(1, BK);

    for (int it = 0; it < NIT; it++) {
        const int slot = it % 3;
        asm volatile("cp.async.wait_group 1;");
        __syncthreads();
        if (it + 2 < NIT) load_stage((it + 2) % 3, (it + 2) * BK);
        else              asm volatile("cp.async.commit_group;");

        const uint32_t base = sbase + (uint32_t)slot * STAGE_B;
        load_frags(base, 0, 0);
        #pragma unroll
        for (int kk = 0; kk < 4; kk++) {
            const int cur = kk & 1;
            if (kk < 3) load_frags(base, kk + 1, cur ^ 1);
            #pragma unroll
            for (int mi = 0; mi < 2; mi++)
                #pragma unroll
                for (int nj = 0; nj < 4; nj++) {
                    const uint32_t* bp = &bfr[cur][nj >> 1][(nj & 1) * 2];
                    MMA_BF16(acc[mi][nj], afr[cur][mi], bp[0], bp[1]);
                }
        }
    }
    __syncthreads();   // all warps done reading smem; reuse as C buffer

    // --- store accumulators to smem C (m16n8 fragment layout)
    const int g = lane >> 2, tt = lane & 3;
    #pragma unroll
    for (int mi = 0; mi < 2; mi++)
        #pragma unroll
        for (int nj = 0; nj < 4; nj++) {
            int row0 = wm * 32 + mi * 16 + g;
            int col  = wn * 32 + nj * 8 + tt * 2;
            *reinterpret_cast<float2*>(&Cf[(size_t)row0 * EPI_LD + col]) =
                make_float2(acc[mi][nj][0], acc[mi][nj][1]);
            *reinterpret_cast<float2*>(&Cf[(size_t)(row0 + 8) * EPI_LD + col]) =
                make_float2(acc[mi][nj][2], acc[mi][nj][3]);
        }
    __syncthreads();

    // --- fused exp + row partial sums: 4 threads per row, 32 cols each
    const int row = t >> 2, seg = t & 3;
    const float* cr = &Cf[(size_t)row * EPI_LD + seg * 32];
    float s = 0.f;
    #pragma unroll
    for (int j = 0; j < 32; j++)
        s += poly_exp(cr[j] * c_invT);
    s += __shfl_xor_sync(0xffffffffu, s, 1);
    s += __shfl_xor_sync(0xffffffffu, s, 2);
    if (seg == 0)
        g_part[(size_t)(by * BM + row) * NTILES + bx] = s;  // deterministic
}

// ---------------------------------------------------------------------------
// Kernel 4a: per-row loss term (8192 threads)
// ---------------------------------------------------------------------------
__global__ void k_rowloss() {
    int b = blockIdx.x * 256 + threadIdx.x;
    const float4* pr = reinterpret_cast<const float4*>(&g_part[(size_t)b * NTILES]);
    float s2s = 0.f;
    #pragma unroll
    for (int j = 0; j < NTILES / 4; j++) {
        float4 v = pr[j];
        s2s += v.x + v.y + v.z + v.w;
    }
    float s2 = s2s * (1.0f / (float)NNEG);
    float s1 = expf(g_pos[b] * c_invT);
    g_row[b] = log1pf(s2 / s1);
}

// ---------------------------------------------------------------------------
// Kernel 4b: final scalar reduce
// ---------------------------------------------------------------------------
__global__ void k_reduce(float* __restrict__ out) {
    int t = threadIdx.x;
    double acc = 0.0;
    #pragma unroll
    for (int j = 0; j < 32; j++)
        acc += (double)g_row[t + j * 256];
    #pragma unroll
    for (int o = 16; o > 0; o >>= 1) acc += __shfl_xor_sync(0xffffffffu, acc, o);
    __shared__ double sd[8];
    if ((t & 31) == 0) sd[t >> 5] = acc;
    __syncthreads();
    if (t == 0) {
        double tot = 0.0;
        #pragma unroll
        for (int i = 0; i < 8; i++) tot += sd[i];
        out[0] = (float)(tot / (double)B_);
    }
}

// ---------------------------------------------------------------------------
extern "C" void kernel_launch(void* const* d_in, const int* in_sizes, int n_in,
                              void* d_out, int out_size) {
    const float* q = (const float*)d_in[0];
    const float* p = (const float*)d_in[1];
    const float* n = (const float*)d_in[2];
    float* out = (float*)d_out;

    cudaFuncSetAttribute(k_gemm, cudaFuncAttributeMaxDynamicSharedMemorySize, SMEM_BYTES);

    k_norm_qp<<<B_, 256>>>(q, p);
    k_norm_n<<<NNEG, 256>>>(n);
    k_gemm<<<dim3(NNEG / BN, B_ / BM), 512, SMEM_BYTES>>>();
    k_rowloss<<<B_ / 256, 256>>>();
    k_reduce<<<1, 256>>>(out);
}